// round 9
// baseline (speedup 1.0000x reference)
#include <cuda_runtime.h>
#include <math.h>

// Problem constants (BasicGcn: N=50000 nodes, E=600000 edges, D=128)
#define NMAX 50000
#define EMAX 600000
#define DDIM 128

// ---------------- device scratch (no allocations allowed) ----------------
__device__ float g_deg[NMAX];
__device__ float g_dinv[NMAX];
__device__ float g_selfnorm[NMAX];
__device__ int   g_cnt[NMAX];
__device__ int   g_rowptr[NMAX];
__device__ int   g_cursor[NMAX];
__device__ int   g_bsums[64];
__device__ int   g_adj_src[EMAX];
__device__ float g_adj_norm[EMAX];
__device__ __align__(16) float g_bufXL[(size_t)NMAX * DDIM];
__device__ __align__(16) float g_bufH[(size_t)NMAX * DDIM];

// ---------------- graph prep ----------------
__global__ void k_node_init(int n) {
    int i = blockIdx.x * blockDim.x + threadIdx.x;
    if (i < n) { g_deg[i] = 1.0f; g_cnt[i] = 0; }
}

// edge_index is INT32 (JAX default config downgrades int64 -> int32).
__global__ void k_edge_pre(const int* __restrict__ ei,
                           const float* __restrict__ w, int e) {
    int idx = blockIdx.x * blockDim.x + threadIdx.x;
    if (idx < e) {
        int c = ei[e + idx];             // target node
        atomicAdd(&g_deg[c], w[idx]);
        atomicAdd(&g_cnt[c], 1);
    }
}

__global__ void k_node_norm(int n) {
    int i = blockIdx.x * blockDim.x + threadIdx.x;
    if (i < n) {
        float d = g_deg[i];              // >= 1 (self loop), always > 0
        float di = rsqrtf(d);
        g_dinv[i] = di;
        g_selfnorm[i] = di * di;         // self-loop norm = 1/deg
    }
}

// ---------------- exclusive scan of g_cnt -> g_rowptr (3 kernels) ----------------
__global__ void k_scan_local(int n) {
    __shared__ int wsum[32];
    int tid = threadIdx.x;
    int i = blockIdx.x * 1024 + tid;
    int v = (i < n) ? g_cnt[i] : 0;
    int lane = tid & 31, wrp = tid >> 5;
    int x = v;
    #pragma unroll
    for (int o = 1; o < 32; o <<= 1) {
        int t = __shfl_up_sync(0xFFFFFFFFu, x, o);
        if (lane >= o) x += t;
    }
    if (lane == 31) wsum[wrp] = x;
    __syncthreads();
    if (wrp == 0) {
        int s = wsum[lane];
        int y = s;
        #pragma unroll
        for (int o = 1; o < 32; o <<= 1) {
            int t = __shfl_up_sync(0xFFFFFFFFu, y, o);
            if (lane >= o) y += t;
        }
        wsum[lane] = y - s;              // exclusive warp offsets
        if (lane == 31) g_bsums[blockIdx.x] = y;   // block total
    }
    __syncthreads();
    if (i < n) g_rowptr[i] = x - v + wsum[wrp];
}

__global__ void k_scan_bsums(int nb) {
    __shared__ int ws[2];
    int tid = threadIdx.x;               // 64 threads
    int lane = tid & 31, wrp = tid >> 5;
    int v = (tid < nb) ? g_bsums[tid] : 0;
    int x = v;
    #pragma unroll
    for (int o = 1; o < 32; o <<= 1) {
        int t = __shfl_up_sync(0xFFFFFFFFu, x, o);
        if (lane >= o) x += t;
    }
    if (lane == 31) ws[wrp] = x;
    __syncthreads();
    int add = (wrp == 1) ? ws[0] : 0;
    if (tid < nb) g_bsums[tid] = x - v + add;   // exclusive block offsets
}

__global__ void k_scan_add(int n) {
    int i = blockIdx.x * blockDim.x + threadIdx.x;
    if (i < n) {
        int rp = g_rowptr[i] + g_bsums[i >> 10];
        g_rowptr[i] = rp;
        g_cursor[i] = rp;
    }
}

__global__ void k_csr_fill(const int* __restrict__ ei,
                           const float* __restrict__ w, int e) {
    int idx = blockIdx.x * blockDim.x + threadIdx.x;
    if (idx < e) {
        int r = ei[idx];                 // source node
        int c = ei[e + idx];             // target node
        int p = atomicAdd(&g_cursor[c], 1);
        g_adj_src[p] = r;
        g_adj_norm[p] = g_dinv[r] * w[idx] * g_dinv[c];
    }
}

// ---------------- SGEMM: g_bufXL[M,128] = A[M,128] @ B[128,128] ----------------
// SRC_GLOBAL=0: A is the param pointer (layer 1 input x). SRC_GLOBAL=1: A is g_bufH.
#define BM 128
#define BK 32
template <int SRC_GLOBAL>
__global__ __launch_bounds__(256) void k_gemm(const float* __restrict__ Aparam,
                                              const float* __restrict__ B,
                                              int M) {
    const float* __restrict__ A = SRC_GLOBAL ? (const float*)g_bufH : Aparam;
    __shared__ float As[BK][BM + 4];
    __shared__ float Bs[BK][128 + 4];
    int tid = threadIdx.x;               // 256
    int tx = tid & 15, ty = tid >> 4;    // 16x16
    int rowBase = blockIdx.x * BM;
    float acc[8][8];
    #pragma unroll
    for (int i = 0; i < 8; i++)
        #pragma unroll
        for (int j = 0; j < 8; j++) acc[i][j] = 0.0f;

    for (int k0 = 0; k0 < 128; k0 += BK) {
        // A tile: 128 rows x 32 k, stored transposed As[k][m]
        #pragma unroll
        for (int it = 0; it < 4; it++) {
            int l = tid + it * 256;      // 0..1023 float4 slots
            int m = l >> 3;              // 0..127
            int kq = l & 7;              // float4 within 32 k
            int gm = rowBase + m;
            float4 v = make_float4(0.f, 0.f, 0.f, 0.f);
            if (gm < M) v = *(const float4*)(A + (size_t)gm * 128 + k0 + kq * 4);
            As[kq * 4 + 0][m] = v.x;
            As[kq * 4 + 1][m] = v.y;
            As[kq * 4 + 2][m] = v.z;
            As[kq * 4 + 3][m] = v.w;
        }
        // B tile: 32 k x 128 n, natural layout
        #pragma unroll
        for (int it = 0; it < 4; it++) {
            int l = tid + it * 256;
            int kk = l >> 5;             // 0..31
            int nq = l & 31;             // float4 col
            float4 v = *(const float4*)(B + (size_t)(k0 + kk) * 128 + nq * 4);
            *(float4*)&Bs[kk][nq * 4] = v;
        }
        __syncthreads();
        #pragma unroll
        for (int kk = 0; kk < BK; kk++) {
            float4 a0 = *(const float4*)&As[kk][ty * 4];
            float4 a1 = *(const float4*)&As[kk][64 + ty * 4];
            float4 b0 = *(const float4*)&Bs[kk][tx * 4];
            float4 b1 = *(const float4*)&Bs[kk][64 + tx * 4];
            float a[8] = {a0.x, a0.y, a0.z, a0.w, a1.x, a1.y, a1.z, a1.w};
            float b[8] = {b0.x, b0.y, b0.z, b0.w, b1.x, b1.y, b1.z, b1.w};
            #pragma unroll
            for (int i = 0; i < 8; i++)
                #pragma unroll
                for (int j = 0; j < 8; j++)
                    acc[i][j] += a[i] * b[j];
        }
        __syncthreads();
    }
    float* __restrict__ C = (float*)g_bufXL;
    #pragma unroll
    for (int i = 0; i < 8; i++) {
        int m = (i < 4) ? (ty * 4 + i) : (64 + ty * 4 + (i - 4));
        int gm = rowBase + m;
        if (gm < M) {
            float4 v0 = make_float4(acc[i][0], acc[i][1], acc[i][2], acc[i][3]);
            float4 v1 = make_float4(acc[i][4], acc[i][5], acc[i][6], acc[i][7]);
            *(float4*)(C + (size_t)gm * 128 + tx * 4) = v0;
            *(float4*)(C + (size_t)gm * 128 + 64 + tx * 4) = v1;
        }
    }
}

// ---------------- aggregation + bias + activation (warp per node) ----------------
// Reads g_bufXL. TO_OUT=0: writes g_bufH. TO_OUT=1: writes param OUT (d_out).
// ACT: 0=ELU, 1=GELU(exact erf), 2=PReLU
template <int ACT, int TO_OUT>
__global__ __launch_bounds__(256) void k_agg(float* __restrict__ OUTparam,
                                             const float* __restrict__ bias,
                                             const float* __restrict__ prelu,
                                             int n) {
    int lane = threadIdx.x & 31;
    int node = blockIdx.x * 8 + (threadIdx.x >> 5);
    if (node >= n) return;
    const float4* __restrict__ XL4 = (const float4*)g_bufXL;

    float4 acc = XL4[(size_t)node * 32 + lane];
    float sn = g_selfnorm[node];
    acc.x *= sn; acc.y *= sn; acc.z *= sn; acc.w *= sn;

    int s = g_rowptr[node];
    int e = s + g_cnt[node];
    int j = s;
    for (; j + 2 <= e; j += 2) {
        int   s0 = g_adj_src[j],     s1 = g_adj_src[j + 1];
        float n0 = g_adj_norm[j],    n1 = g_adj_norm[j + 1];
        float4 v0 = XL4[(size_t)s0 * 32 + lane];
        float4 v1 = XL4[(size_t)s1 * 32 + lane];
        acc.x += n0 * v0.x + n1 * v1.x;
        acc.y += n0 * v0.y + n1 * v1.y;
        acc.z += n0 * v0.z + n1 * v1.z;
        acc.w += n0 * v0.w + n1 * v1.w;
    }
    if (j < e) {
        int   s0 = g_adj_src[j];
        float n0 = g_adj_norm[j];
        float4 v0 = XL4[(size_t)s0 * 32 + lane];
        acc.x += n0 * v0.x; acc.y += n0 * v0.y;
        acc.z += n0 * v0.z; acc.w += n0 * v0.w;
    }

    float4 bb = ((const float4*)bias)[lane];
    float r[4] = {acc.x + bb.x, acc.y + bb.y, acc.z + bb.z, acc.w + bb.w};

    if (ACT == 0) {          // ELU
        #pragma unroll
        for (int k = 0; k < 4; k++) r[k] = (r[k] > 0.f) ? r[k] : expm1f(r[k]);
    } else if (ACT == 1) {   // GELU exact
        #pragma unroll
        for (int k = 0; k < 4; k++)
            r[k] = 0.5f * r[k] * (1.0f + erff(r[k] * 0.70710678118654752f));
    } else {                 // PReLU
        float a = *prelu;
        #pragma unroll
        for (int k = 0; k < 4; k++) r[k] = (r[k] >= 0.f) ? r[k] : a * r[k];
    }
    float4* __restrict__ OUT4 = TO_OUT ? (float4*)OUTparam : (float4*)g_bufH;
    OUT4[(size_t)node * 32 + lane] = make_float4(r[0], r[1], r[2], r[3]);
}

// ---------------- launch (kernel launches ONLY — fully capture-safe) ----------------
extern "C" void kernel_launch(void* const* d_in, const int* in_sizes, int n_in,
                              void* d_out, int out_size) {
    const float* x  = (const float*)d_in[0];
    const int*   ei = (const int*)d_in[1];     // int32! (JAX x64 disabled)
    const float* w  = (const float*)d_in[2];
    const float* W1 = (const float*)d_in[3];
    const float* b1 = (const float*)d_in[4];
    const float* W2 = (const float*)d_in[5];
    const float* b2 = (const float*)d_in[6];
    const float* W3 = (const float*)d_in[7];
    const float* b3 = (const float*)d_in[8];
    const float* pr = (const float*)d_in[9];

    int n = in_sizes[0] / DDIM;          // 50000
    int e = in_sizes[2];                 // 600000

    int nb256  = (n + 255) / 256;
    int eb256  = (e + 255) / 256;
    int nblk   = (n + 1023) / 1024;
    int gemmGrid = (n + BM - 1) / BM;
    int aggGrid  = (n + 7) / 8;

    // graph normalization + CSR (redone every launch: deterministic, cheap)
    k_node_init<<<nb256, 256>>>(n);
    k_edge_pre<<<eb256, 256>>>(ei, w, e);
    k_node_norm<<<nb256, 256>>>(n);
    k_scan_local<<<nblk, 1024>>>(n);
    k_scan_bsums<<<1, 64>>>(nblk);
    k_scan_add<<<nb256, 256>>>(n);
    k_csr_fill<<<eb256, 256>>>(ei, w, e);

    // layer 1: GCN -> ELU
    k_gemm<0><<<gemmGrid, 256>>>(x, W1, n);
    k_agg<0, 0><<<aggGrid, 256>>>(nullptr, b1, pr, n);
    // layer 2: GCN -> GELU (exact)
    k_gemm<1><<<gemmGrid, 256>>>(nullptr, W2, n);
    k_agg<1, 0><<<aggGrid, 256>>>(nullptr, b2, pr, n);
    // layer 3: GCN -> PReLU
    k_gemm<1><<<gemmGrid, 256>>>(nullptr, W3, n);
    k_agg<2, 1><<<aggGrid, 256>>>((float*)d_out, b3, pr, n);
}

// round 15
// speedup vs baseline: 1.1801x; 1.1801x over previous
#include <cuda_runtime.h>
#include <cuda_bf16.h>
#include <math.h>
#include <stdint.h>

// Problem constants (BasicGcn: N=50000 nodes, E=600000 edges, D=128)
#define NMAX 50000
#define EMAX 600000
#define DDIM 128

// ---------------- device scratch (no allocations allowed) ----------------
__device__ float g_deg[NMAX];
__device__ float g_dinv[NMAX];
__device__ float g_selfnorm[NMAX];
__device__ int   g_cnt[NMAX];
__device__ int   g_rowptr[NMAX];
__device__ int   g_cursor[NMAX];
__device__ int   g_bsums[64];
__device__ int   g_adj_src[EMAX];
__device__ float g_adj_norm[EMAX];
__device__ __align__(16) float         g_bufXL[(size_t)NMAX * DDIM];
__device__ __align__(16) __nv_bfloat16 g_aHi[(size_t)NMAX * DDIM];
__device__ __align__(16) __nv_bfloat16 g_aLo[(size_t)NMAX * DDIM];

// ---------------- helpers ----------------
__device__ __forceinline__ uint32_t smem_to_u32(const void* p) {
    uint32_t a;
    asm("{ .reg .u64 t; cvta.to.shared.u64 t, %1; cvt.u32.u64 %0, t; }" : "=r"(a) : "l"(p));
    return a;
}
__device__ __forceinline__ void ldsm4(uint32_t* r, uint32_t addr) {
    asm volatile("ldmatrix.sync.aligned.m8n8.x4.shared.b16 {%0,%1,%2,%3}, [%4];"
                 : "=r"(r[0]), "=r"(r[1]), "=r"(r[2]), "=r"(r[3]) : "r"(addr));
}
__device__ __forceinline__ void mma_bf16(float* d, const uint32_t* a, const uint32_t* b) {
    asm volatile(
        "mma.sync.aligned.m16n8k16.row.col.f32.bf16.bf16.f32 "
        "{%0,%1,%2,%3}, {%4,%5,%6,%7}, {%8,%9}, {%0,%1,%2,%3};"
        : "+f"(d[0]), "+f"(d[1]), "+f"(d[2]), "+f"(d[3])
        : "r"(a[0]), "r"(a[1]), "r"(a[2]), "r"(a[3]), "r"(b[0]), "r"(b[1]));
}

// ---------------- graph prep ----------------
__global__ void k_node_init(int n) {
    int i = blockIdx.x * blockDim.x + threadIdx.x;
    if (i < n) { g_deg[i] = 1.0f; g_cnt[i] = 0; }
}

__global__ void k_edge_pre(const int* __restrict__ ei,
                           const float* __restrict__ w, int e) {
    int idx = blockIdx.x * blockDim.x + threadIdx.x;
    if (idx < e) {
        int c = ei[e + idx];
        atomicAdd(&g_deg[c], w[idx]);
        atomicAdd(&g_cnt[c], 1);
    }
}

__global__ void k_node_norm(int n) {
    int i = blockIdx.x * blockDim.x + threadIdx.x;
    if (i < n) {
        float di = rsqrtf(g_deg[i]);
        g_dinv[i] = di;
        g_selfnorm[i] = di * di;
    }
}

__global__ void k_scan_local(int n) {
    __shared__ int wsum[32];
    int tid = threadIdx.x;
    int i = blockIdx.x * 1024 + tid;
    int v = (i < n) ? g_cnt[i] : 0;
    int lane = tid & 31, wrp = tid >> 5;
    int x = v;
    #pragma unroll
    for (int o = 1; o < 32; o <<= 1) {
        int t = __shfl_up_sync(0xFFFFFFFFu, x, o);
        if (lane >= o) x += t;
    }
    if (lane == 31) wsum[wrp] = x;
    __syncthreads();
    if (wrp == 0) {
        int s = wsum[lane];
        int y = s;
        #pragma unroll
        for (int o = 1; o < 32; o <<= 1) {
            int t = __shfl_up_sync(0xFFFFFFFFu, y, o);
            if (lane >= o) y += t;
        }
        wsum[lane] = y - s;
        if (lane == 31) g_bsums[blockIdx.x] = y;
    }
    __syncthreads();
    if (i < n) g_rowptr[i] = x - v + wsum[wrp];
}

__global__ void k_scan_bsums(int nb) {
    __shared__ int ws[2];
    int tid = threadIdx.x;
    int lane = tid & 31, wrp = tid >> 5;
    int v = (tid < nb) ? g_bsums[tid] : 0;
    int x = v;
    #pragma unroll
    for (int o = 1; o < 32; o <<= 1) {
        int t = __shfl_up_sync(0xFFFFFFFFu, x, o);
        if (lane >= o) x += t;
    }
    if (lane == 31) ws[wrp] = x;
    __syncthreads();
    int add = (wrp == 1) ? ws[0] : 0;
    if (tid < nb) g_bsums[tid] = x - v + add;
}

__global__ void k_scan_add(int n) {
    int i = blockIdx.x * blockDim.x + threadIdx.x;
    if (i < n) {
        int rp = g_rowptr[i] + g_bsums[i >> 10];
        g_rowptr[i] = rp;
        g_cursor[i] = rp;
    }
}

__global__ void k_csr_fill(const int* __restrict__ ei,
                           const float* __restrict__ w, int e) {
    int idx = blockIdx.x * blockDim.x + threadIdx.x;
    if (idx < e) {
        int r = ei[idx];
        int c = ei[e + idx];
        int p = atomicAdd(&g_cursor[c], 1);
        g_adj_src[p] = r;
        g_adj_norm[p] = g_dinv[r] * w[idx] * g_dinv[c];
    }
}

// ---------------- split x -> bf16 hi/lo ----------------
__global__ void k_split_x(const float* __restrict__ x, int total4) {
    int i = blockIdx.x * blockDim.x + threadIdx.x;
    if (i < total4) {
        float4 v = ((const float4*)x)[i];
        float vv[4] = {v.x, v.y, v.z, v.w};
        union { __nv_bfloat16 b[4]; ushort4 u; } H, L;
        #pragma unroll
        for (int k = 0; k < 4; k++) {
            H.b[k] = __float2bfloat16(vv[k]);
            L.b[k] = __float2bfloat16(vv[k] - __bfloat162float(H.b[k]));
        }
        *(ushort4*)(&g_aHi[(size_t)i * 4]) = H.u;
        *(ushort4*)(&g_aLo[(size_t)i * 4]) = L.u;
    }
}

// ---------------- HMMA bf16-split GEMM: g_bufXL[M,128] = (aHi+aLo) @ W -------------
// Persistent grid. W split+transposed to WT[N][K] bf16 hi/lo in SMEM (resident).
// Per 128-row tile: stage A hi/lo, then 8 warps (2Mx4N) compute 64x32 warp tiles
// via mma.m16n8k16 with 3 products: Ah*Wh + Ah*Wl + Al*Wh (err ~2^-17).
// SMEM stride: 136 bf16 = 272B per row -> ldmatrix conflict-free (row step 4 banks).
#define SROW 136
#define SROWB 272
#define SM_WH 0
#define SM_WL 34816
#define SM_AH 69632
#define SM_AL 104448
#define GSMEM 139264

__global__ __launch_bounds__(256, 1) void k_gemm_mma(const float* __restrict__ W,
                                                     int M, int numTiles) {
    extern __shared__ char smem[];
    uint32_t sb = smem_to_u32(smem);
    int tid = threadIdx.x;
    int lane = tid & 31, wid = tid >> 5;
    int warp_m = wid >> 2, warp_n = wid & 3;   // 2 x 4 warp grid

    // ---- W split + transpose: WT[n][k] bf16 hi/lo (one time, persistent) ----
    #pragma unroll 4
    for (int j = 0; j < 64; j++) {
        int i = tid + j * 256;               // 16384 elements of W[k][n]
        int k = i >> 7, nn = i & 127;
        float wv = W[i];
        __nv_bfloat16 hi = __float2bfloat16(wv);
        __nv_bfloat16 lo = __float2bfloat16(wv - __bfloat162float(hi));
        uint32_t off = (uint32_t)nn * SROWB + (uint32_t)k * 2;
        *(__nv_bfloat16*)(smem + SM_WH + off) = hi;
        *(__nv_bfloat16*)(smem + SM_WL + off) = lo;
    }

    // ---- per-thread ldmatrix lane addressing ----
    // A frag (16x16): lanes 0-7 rows 0-7 k0 | 8-15 rows 8-15 k0 | 16-23 rows 0-7 k8 | 24-31 rows 8-15 k8
    uint32_t a_row  = (uint32_t)(warp_m * 64 + (lane & 15));
    uint32_t a_koff = (uint32_t)((lane >> 4) * 8);
    uint32_t aoff[4];
    #pragma unroll
    for (int mt = 0; mt < 4; mt++)
        aoff[mt] = (a_row + mt * 16) * SROWB + a_koff * 2;
    // B frag pair (two 8-col n-tiles x 16k): lg0 (n0-7,k0) lg1 (n0-7,k8) lg2 (n8-15,k0) lg3 (n8-15,k8)
    uint32_t b_n = (uint32_t)(warp_n * 32 + (lane & 7) + ((lane >> 4) << 3));
    uint32_t b_k = (uint32_t)(((lane >> 3) & 1) * 8);
    uint32_t boff[2];
    #pragma unroll
    for (int np = 0; np < 2; np++)
        boff[np] = (b_n + np * 16) * SROWB + b_k * 2;

    const uint4* GH = (const uint4*)g_aHi;
    const uint4* GL = (const uint4*)g_aLo;

    for (int tile = blockIdx.x; tile < numTiles; tile += gridDim.x) {
        int rowBase = tile * 128;
        // ---- stage A hi/lo tile (128 x 128 bf16 each) ----
        #pragma unroll
        for (int j = 0; j < 8; j++) {
            int i = tid + j * 256;           // 2048 uint4 slots
            int r = i >> 4, q = i & 15;      // row, 8-elem group
            int gm = rowBase + r;
            uint4 vh = make_uint4(0, 0, 0, 0), vl = make_uint4(0, 0, 0, 0);
            if (gm < M) {
                size_t gi = (size_t)gm * 16 + q;
                vh = GH[gi]; vl = GL[gi];
            }
            uint32_t off = (uint32_t)r * SROWB + (uint32_t)q * 16;
            *(uint4*)(smem + SM_AH + off) = vh;
            *(uint4*)(smem + SM_AL + off) = vl;
        }
        __syncthreads();

        // ---- compute 64x32 warp tile ----
        float d[4][4][4];
        #pragma unroll
        for (int mt = 0; mt < 4; mt++)
            #pragma unroll
            for (int nt = 0; nt < 4; nt++)
                #pragma unroll
                for (int q = 0; q < 4; q++) d[mt][nt][q] = 0.0f;

        #pragma unroll
        for (int ks = 0; ks < 8; ks++) {
            uint32_t kb = ks * 32;           // 16 k * 2B
            uint32_t ah[4][4], al[4][4], bh[2][4], bl[2][4];
            #pragma unroll
            for (int mt = 0; mt < 4; mt++) {
                ldsm4(ah[mt], sb + SM_AH + aoff[mt] + kb);
                ldsm4(al[mt], sb + SM_AL + aoff[mt] + kb);
            }
            #pragma unroll
            for (int np = 0; np < 2; np++) {
                ldsm4(bh[np], sb + SM_WH + boff[np] + kb);
                ldsm4(bl[np], sb + SM_WL + boff[np] + kb);
            }
            #pragma unroll
            for (int mt = 0; mt < 4; mt++)
                #pragma unroll
                for (int nt = 0; nt < 4; nt++) {
                    const uint32_t* ph = &bh[nt >> 1][(nt & 1) * 2];
                    const uint32_t* pl = &bl[nt >> 1][(nt & 1) * 2];
                    mma_bf16(d[mt][nt], ah[mt], ph);
                    mma_bf16(d[mt][nt], ah[mt], pl);
                    mma_bf16(d[mt][nt], al[mt], ph);
                }
        }

        // ---- epilogue: fp32 to g_bufXL ----
        int g = lane >> 2, c = (lane & 3) * 2;
        #pragma unroll
        for (int mt = 0; mt < 4; mt++) {
            int row0 = rowBase + warp_m * 64 + mt * 16 + g;
            int row1 = row0 + 8;
            #pragma unroll
            for (int nt = 0; nt < 4; nt++) {
                int col = warp_n * 32 + nt * 8 + c;
                if (row0 < M)
                    *(float2*)(g_bufXL + (size_t)row0 * 128 + col) =
                        make_float2(d[mt][nt][0], d[mt][nt][1]);
                if (row1 < M)
                    *(float2*)(g_bufXL + (size_t)row1 * 128 + col) =
                        make_float2(d[mt][nt][2], d[mt][nt][3]);
            }
        }
        __syncthreads();                     // A tiles reused next iteration
    }
}

// ---------------- aggregation + bias + activation (warp per node) ----------------
// Reads g_bufXL. WMODE=0: write bf16 splits (g_aHi/g_aLo). WMODE=1: fp32 to OUT.
// ACT: 0=ELU, 1=GELU(exact erf), 2=PReLU
template <int ACT, int WMODE>
__global__ __launch_bounds__(256) void k_agg(float* __restrict__ OUTparam,
                                             const float* __restrict__ bias,
                                             const float* __restrict__ prelu,
                                             int n) {
    int lane = threadIdx.x & 31;
    int node = blockIdx.x * 8 + (threadIdx.x >> 5);
    if (node >= n) return;
    const float4* __restrict__ XL4 = (const float4*)g_bufXL;

    float4 acc = XL4[(size_t)node * 32 + lane];
    float sn = g_selfnorm[node];
    acc.x *= sn; acc.y *= sn; acc.z *= sn; acc.w *= sn;

    int s = g_rowptr[node];
    int e = s + g_cnt[node];
    int j = s;
    for (; j + 2 <= e; j += 2) {
        int   s0 = g_adj_src[j],  s1 = g_adj_src[j + 1];
        float n0 = g_adj_norm[j], n1 = g_adj_norm[j + 1];
        float4 v0 = XL4[(size_t)s0 * 32 + lane];
        float4 v1 = XL4[(size_t)s1 * 32 + lane];
        acc.x += n0 * v0.x + n1 * v1.x;
        acc.y += n0 * v0.y + n1 * v1.y;
        acc.z += n0 * v0.z + n1 * v1.z;
        acc.w += n0 * v0.w + n1 * v1.w;
    }
    if (j < e) {
        int   s0 = g_adj_src[j];
        float n0 = g_adj_norm[j];
        float4 v0 = XL4[(size_t)s0 * 32 + lane];
        acc.x += n0 * v0.x; acc.y += n0 * v0.y;
        acc.z += n0 * v0.z; acc.w += n0 * v0.w;
    }

    float4 bb = ((const float4*)bias)[lane];
    float r[4] = {acc.x + bb.x, acc.y + bb.y, acc.z + bb.z, acc.w + bb.w};

    if (ACT == 0) {
        #pragma unroll
        for (int k = 0; k < 4; k++) r[k] = (r[k] > 0.f) ? r[k] : expm1f(r[k]);
    } else if (ACT == 1) {
        #pragma unroll
        for (int k = 0; k < 4; k++)
            r[k] = 0.5f * r[k] * (1.0f + erff(r[k] * 0.70710678118654752f));
    } else {
        float a = *prelu;
        #pragma unroll
        for (int k = 0; k < 4; k++) r[k] = (r[k] >= 0.f) ? r[k] : a * r[k];
    }

    if (WMODE == 0) {
        union { __nv_bfloat16 b[4]; ushort4 u; } H, L;
        #pragma unroll
        for (int k = 0; k < 4; k++) {
            H.b[k] = __float2bfloat16(r[k]);
            L.b[k] = __float2bfloat16(r[k] - __bfloat162float(H.b[k]));
        }
        size_t off = (size_t)node * 128 + lane * 4;
        *(ushort4*)(&g_aHi[off]) = H.u;
        *(ushort4*)(&g_aLo[off]) = L.u;
    } else {
        ((float4*)OUTparam)[(size_t)node * 32 + lane] = make_float4(r[0], r[1], r[2], r[3]);
    }
}

// ---------------- launch ----------------
extern "C" void kernel_launch(void* const* d_in, const int* in_sizes, int n_in,
                              void* d_out, int out_size) {
    const float* x  = (const float*)d_in[0];
    const int*   ei = (const int*)d_in[1];
    const float* w  = (const float*)d_in[2];
    const float* W1 = (const float*)d_in[3];
    const float* b1 = (const float*)d_in[4];
    const float* W2 = (const float*)d_in[5];
    const float* b2 = (const float*)d_in[6];
    const float* W3 = (const float*)d_in[7];
    const float* b3 = (const float*)d_in[8];
    const float* pr = (const float*)d_in[9];

    int n = in_sizes[0] / DDIM;          // 50000
    int e = in_sizes[2];                 // 600000

    int nb256 = (n + 255) / 256;
    int eb256 = (e + 255) / 256;
    int nblk  = (n + 1023) / 1024;
    int numTiles = (n + 127) / 128;      // 391
    int aggGrid  = (n + 7) / 8;
    int splitGrid = (n * 32 + 255) / 256;
    int gemmGrid = numTiles < 148 ? numTiles : 148;

    cudaFuncSetAttribute(k_gemm_mma, cudaFuncAttributeMaxDynamicSharedMemorySize, GSMEM);

    // graph normalization + CSR
    k_node_init<<<nb256, 256>>>(n);
    k_edge_pre<<<eb256, 256>>>(ei, w, e);
    k_node_norm<<<nb256, 256>>>(n);
    k_scan_local<<<nblk, 1024>>>(n);
    k_scan_bsums<<<1, 64>>>(nblk);
    k_scan_add<<<nb256, 256>>>(n);
    k_csr_fill<<<eb256, 256>>>(ei, w, e);

    // input split
    k_split_x<<<splitGrid, 256>>>(x, n * 32);

    // layer 1: GCN -> ELU
    k_gemm_mma<<<gemmGrid, 256, GSMEM>>>(W1, n, numTiles);
    k_agg<0, 0><<<aggGrid, 256>>>(nullptr, b1, pr, n);
    // layer 2: GCN -> GELU (exact)
    k_gemm_mma<<<gemmGrid, 256, GSMEM>>>(W2, n, numTiles);
    k_agg<1, 0><<<aggGrid, 256>>>(nullptr, b2, pr, n);
    // layer 3: GCN -> PReLU
    k_gemm_mma<<<gemmGrid, 256, GSMEM>>>(W3, n, numTiles);
    k_agg<2, 1><<<aggGrid, 256>>>((float*)d_out, b3, pr, n);
}

// round 16
// speedup vs baseline: 1.2437x; 1.0539x over previous
#include <cuda_runtime.h>
#include <cuda_bf16.h>
#include <cuda_fp16.h>
#include <math.h>
#include <stdint.h>

// Problem constants (BasicGcn: N=50000 nodes, E=600000 edges, D=128)
#define NMAX 50000
#define EMAX 600000
#define DDIM 128

// ---------------- device scratch (no allocations allowed) ----------------
__device__ float g_deg[NMAX];
__device__ float g_dinv[NMAX];
__device__ float g_selfnorm[NMAX];
__device__ int   g_cnt[NMAX];
__device__ int   g_rowptr[NMAX];
__device__ int   g_cursor[NMAX];
__device__ int   g_bsums[256];
__device__ int   g_adj_src[EMAX];
__device__ float g_adj_norm[EMAX];
__device__ __align__(16) __half        g_xlH[(size_t)NMAX * DDIM];   // GEMM out (fp16)
__device__ __align__(16) __nv_bfloat16 g_aHi[(size_t)NMAX * DDIM];   // GEMM in hi
__device__ __align__(16) __nv_bfloat16 g_aLo[(size_t)NMAX * DDIM];   // GEMM in lo

// ---------------- helpers ----------------
__device__ __forceinline__ uint32_t smem_to_u32(const void* p) {
    uint32_t a;
    asm("{ .reg .u64 t; cvta.to.shared.u64 t, %1; cvt.u32.u64 %0, t; }" : "=r"(a) : "l"(p));
    return a;
}
__device__ __forceinline__ void ldsm4(uint32_t* r, uint32_t addr) {
    asm volatile("ldmatrix.sync.aligned.m8n8.x4.shared.b16 {%0,%1,%2,%3}, [%4];"
                 : "=r"(r[0]), "=r"(r[1]), "=r"(r[2]), "=r"(r[3]) : "r"(addr));
}
__device__ __forceinline__ void mma_bf16(float* d, const uint32_t* a, const uint32_t* b) {
    asm volatile(
        "mma.sync.aligned.m16n8k16.row.col.f32.bf16.bf16.f32 "
        "{%0,%1,%2,%3}, {%4,%5,%6,%7}, {%8,%9}, {%0,%1,%2,%3};"
        : "+f"(d[0]), "+f"(d[1]), "+f"(d[2]), "+f"(d[3])
        : "r"(a[0]), "r"(a[1]), "r"(a[2]), "r"(a[3]), "r"(b[0]), "r"(b[1]));
}

// ---------------- graph prep ----------------
__global__ void k_node_init(int n) {
    int i = blockIdx.x * blockDim.x + threadIdx.x;
    if (i < n) { g_deg[i] = 1.0f; g_cnt[i] = 0; }
}

__global__ void k_edge_pre(const int* __restrict__ ei,
                           const float* __restrict__ w, int e) {
    int idx = blockIdx.x * blockDim.x + threadIdx.x;
    if (idx < e) {
        int c = ei[e + idx];
        atomicAdd(&g_deg[c], w[idx]);
        atomicAdd(&g_cnt[c], 1);
    }
}

// exclusive scan of g_cnt -> g_rowptr, 256 elems/block (196 blocks -> full chip)
__global__ void k_scan_local(int n) {
    __shared__ int wsum[8];
    int tid = threadIdx.x;
    int i = blockIdx.x * 256 + tid;
    int v = (i < n) ? g_cnt[i] : 0;
    int lane = tid & 31, wrp = tid >> 5;
    int x = v;
    #pragma unroll
    for (int o = 1; o < 32; o <<= 1) {
        int t = __shfl_up_sync(0xFFFFFFFFu, x, o);
        if (lane >= o) x += t;
    }
    if (lane == 31) wsum[wrp] = x;
    __syncthreads();
    if (wrp == 0 && lane < 8) {
        int s = wsum[lane];
        int y = s;
        #pragma unroll
        for (int o = 1; o < 8; o <<= 1) {
            int t = __shfl_up_sync(0xFFu, y, o, 8);
            if (lane >= o) y += t;
        }
        wsum[lane] = y - s;              // exclusive warp offsets
        if (lane == 7) g_bsums[blockIdx.x] = y;   // block total
    }
    __syncthreads();
    if (i < n) g_rowptr[i] = x - v + wsum[wrp];
}

__global__ void k_scan_bsums(int nb) {   // nb <= 256, one block of 256
    __shared__ int ws[8];
    int tid = threadIdx.x;
    int lane = tid & 31, wrp = tid >> 5;
    int v = (tid < nb) ? g_bsums[tid] : 0;
    int x = v;
    #pragma unroll
    for (int o = 1; o < 32; o <<= 1) {
        int t = __shfl_up_sync(0xFFFFFFFFu, x, o);
        if (lane >= o) x += t;
    }
    if (lane == 31) ws[wrp] = x;
    __syncthreads();
    if (wrp == 0 && lane < 8) {
        int s = ws[lane];
        int y = s;
        #pragma unroll
        for (int o = 1; o < 8; o <<= 1) {
            int t = __shfl_up_sync(0xFFu, y, o, 8);
            if (lane >= o) y += t;
        }
        ws[lane] = y - s;
    }
    __syncthreads();
    if (tid < nb) g_bsums[tid] = x - v + ws[wrp];
}

// fold per-node normalization into the scan finalize (one fewer launch)
__global__ void k_scan_add_norm(int n) {
    int i = blockIdx.x * blockDim.x + threadIdx.x;
    if (i < n) {
        int rp = g_rowptr[i] + g_bsums[i >> 8];
        g_rowptr[i] = rp;
        g_cursor[i] = rp;
        float di = rsqrtf(g_deg[i]);
        g_dinv[i] = di;
        g_selfnorm[i] = di * di;
    }
}

__global__ void k_csr_fill(const int* __restrict__ ei,
                           const float* __restrict__ w, int e) {
    int idx = blockIdx.x * blockDim.x + threadIdx.x;
    if (idx < e) {
        int r = ei[idx];
        int c = ei[e + idx];
        int p = atomicAdd(&g_cursor[c], 1);
        g_adj_src[p] = r;
        g_adj_norm[p] = g_dinv[r] * w[idx] * g_dinv[c];
    }
}

// ---------------- split x -> bf16 hi/lo ----------------
__global__ void k_split_x(const float* __restrict__ x, int total4) {
    int i = blockIdx.x * blockDim.x + threadIdx.x;
    if (i < total4) {
        float4 v = ((const float4*)x)[i];
        float vv[4] = {v.x, v.y, v.z, v.w};
        union { __nv_bfloat16 b[4]; ushort4 u; } H, L;
        #pragma unroll
        for (int k = 0; k < 4; k++) {
            H.b[k] = __float2bfloat16(vv[k]);
            L.b[k] = __float2bfloat16(vv[k] - __bfloat162float(H.b[k]));
        }
        *(ushort4*)(&g_aHi[(size_t)i * 4]) = H.u;
        *(ushort4*)(&g_aLo[(size_t)i * 4]) = L.u;
    }
}

// ---------------- HMMA bf16-split GEMM: g_xlH[M,128] = (aHi+aLo) @ W -------------
// Persistent grid. W split+transposed to WT[N][K] bf16 hi/lo in SMEM (resident).
// Per 128-row tile: stage A hi/lo, 8 warps (2Mx4N) -> 64x32 warp tiles via
// mma.m16n8k16 with 3 products Ah*Wh + Ah*Wl + Al*Wh (err ~2^-17).
// Epilogue writes fp16 (feeds the L2-bound gather at half traffic).
#define SROW 136
#define SROWB 272
#define SM_WH 0
#define SM_WL 34816
#define SM_AH 69632
#define SM_AL 104448
#define GSMEM 139264

__global__ __launch_bounds__(256, 1) void k_gemm_mma(const float* __restrict__ W,
                                                     int M, int numTiles) {
    extern __shared__ char smem[];
    uint32_t sb = smem_to_u32(smem);
    int tid = threadIdx.x;
    int lane = tid & 31, wid = tid >> 5;
    int warp_m = wid >> 2, warp_n = wid & 3;   // 2 x 4 warp grid

    // ---- W split + transpose: WT[n][k] bf16 hi/lo (once; persistent) ----
    #pragma unroll 4
    for (int j = 0; j < 64; j++) {
        int i = tid + j * 256;               // 16384 elements of W[k][n]
        int k = i >> 7, nn = i & 127;
        float wv = W[i];
        __nv_bfloat16 hi = __float2bfloat16(wv);
        __nv_bfloat16 lo = __float2bfloat16(wv - __bfloat162float(hi));
        uint32_t off = (uint32_t)nn * SROWB + (uint32_t)k * 2;
        *(__nv_bfloat16*)(smem + SM_WH + off) = hi;
        *(__nv_bfloat16*)(smem + SM_WL + off) = lo;
    }

    // ---- ldmatrix lane addressing ----
    uint32_t a_row  = (uint32_t)(warp_m * 64 + (lane & 15));
    uint32_t a_koff = (uint32_t)((lane >> 4) * 8);
    uint32_t aoff[4];
    #pragma unroll
    for (int mt = 0; mt < 4; mt++)
        aoff[mt] = (a_row + mt * 16) * SROWB + a_koff * 2;
    uint32_t b_n = (uint32_t)(warp_n * 32 + (lane & 7) + ((lane >> 4) << 3));
    uint32_t b_k = (uint32_t)(((lane >> 3) & 1) * 8);
    uint32_t boff[2];
    #pragma unroll
    for (int np = 0; np < 2; np++)
        boff[np] = (b_n + np * 16) * SROWB + b_k * 2;

    const uint4* GH = (const uint4*)g_aHi;
    const uint4* GL = (const uint4*)g_aLo;

    for (int tile = blockIdx.x; tile < numTiles; tile += gridDim.x) {
        int rowBase = tile * 128;
        // ---- stage A hi/lo tile ----
        #pragma unroll
        for (int j = 0; j < 8; j++) {
            int i = tid + j * 256;
            int r = i >> 4, q = i & 15;
            int gm = rowBase + r;
            uint4 vh = make_uint4(0, 0, 0, 0), vl = make_uint4(0, 0, 0, 0);
            if (gm < M) {
                size_t gi = (size_t)gm * 16 + q;
                vh = GH[gi]; vl = GL[gi];
            }
            uint32_t off = (uint32_t)r * SROWB + (uint32_t)q * 16;
            *(uint4*)(smem + SM_AH + off) = vh;
            *(uint4*)(smem + SM_AL + off) = vl;
        }
        __syncthreads();

        // ---- compute 64x32 warp tile ----
        float d[4][4][4];
        #pragma unroll
        for (int mt = 0; mt < 4; mt++)
            #pragma unroll
            for (int nt = 0; nt < 4; nt++)
                #pragma unroll
                for (int q = 0; q < 4; q++) d[mt][nt][q] = 0.0f;

        #pragma unroll
        for (int ks = 0; ks < 8; ks++) {
            uint32_t kb = ks * 32;
            uint32_t ah[4][4], al[4][4], bh[2][4], bl[2][4];
            #pragma unroll
            for (int mt = 0; mt < 4; mt++) {
                ldsm4(ah[mt], sb + SM_AH + aoff[mt] + kb);
                ldsm4(al[mt], sb + SM_AL + aoff[mt] + kb);
            }
            #pragma unroll
            for (int np = 0; np < 2; np++) {
                ldsm4(bh[np], sb + SM_WH + boff[np] + kb);
                ldsm4(bl[np], sb + SM_WL + boff[np] + kb);
            }
            #pragma unroll
            for (int mt = 0; mt < 4; mt++)
                #pragma unroll
                for (int nt = 0; nt < 4; nt++) {
                    const uint32_t* ph = &bh[nt >> 1][(nt & 1) * 2];
                    const uint32_t* pl = &bl[nt >> 1][(nt & 1) * 2];
                    mma_bf16(d[mt][nt], ah[mt], ph);
                    mma_bf16(d[mt][nt], ah[mt], pl);
                    mma_bf16(d[mt][nt], al[mt], ph);
                }
        }

        // ---- epilogue: fp16 to g_xlH ----
        int g = lane >> 2, c = (lane & 3) * 2;
        #pragma unroll
        for (int mt = 0; mt < 4; mt++) {
            int row0 = rowBase + warp_m * 64 + mt * 16 + g;
            int row1 = row0 + 8;
            #pragma unroll
            for (int nt = 0; nt < 4; nt++) {
                int col = warp_n * 32 + nt * 8 + c;
                if (row0 < M)
                    *(__half2*)(g_xlH + (size_t)row0 * 128 + col) =
                        __floats2half2_rn(d[mt][nt][0], d[mt][nt][1]);
                if (row1 < M)
                    *(__half2*)(g_xlH + (size_t)row1 * 128 + col) =
                        __floats2half2_rn(d[mt][nt][2], d[mt][nt][3]);
            }
        }
        __syncthreads();
    }
}

// ---------------- aggregation + bias + activation (warp per node) ----------------
// Gathers fp16 rows (256B/edge, half the fp32 traffic). fp32 accumulate.
// WMODE=0: write bf16 splits. WMODE=1: fp32 to OUT. ACT: 0=ELU 1=GELU 2=PReLU
template <int ACT, int WMODE>
__global__ __launch_bounds__(256) void k_agg(float* __restrict__ OUTparam,
                                             const float* __restrict__ bias,
                                             const float* __restrict__ prelu,
                                             int n) {
    int lane = threadIdx.x & 31;
    int node = blockIdx.x * 8 + (threadIdx.x >> 5);
    if (node >= n) return;
    const __half* __restrict__ XH = g_xlH;

    float a0, a1, a2, a3;
    {
        uint2 u = *(const uint2*)(XH + (size_t)node * 128 + lane * 4);
        float2 f0 = __half22float2(*reinterpret_cast<__half2*>(&u.x));
        float2 f1 = __half22float2(*reinterpret_cast<__half2*>(&u.y));
        float sn = g_selfnorm[node];
        a0 = f0.x * sn; a1 = f0.y * sn; a2 = f1.x * sn; a3 = f1.y * sn;
    }

    int s = g_rowptr[node];
    int e = s + g_cnt[node];
    int j = s;
    for (; j + 2 <= e; j += 2) {
        int   s0 = g_adj_src[j],  s1 = g_adj_src[j + 1];
        float n0 = g_adj_norm[j], n1 = g_adj_norm[j + 1];
        uint2 u0 = *(const uint2*)(XH + (size_t)s0 * 128 + lane * 4);
        uint2 u1 = *(const uint2*)(XH + (size_t)s1 * 128 + lane * 4);
        float2 p0 = __half22float2(*reinterpret_cast<__half2*>(&u0.x));
        float2 p1 = __half22float2(*reinterpret_cast<__half2*>(&u0.y));
        float2 q0 = __half22float2(*reinterpret_cast<__half2*>(&u1.x));
        float2 q1 = __half22float2(*reinterpret_cast<__half2*>(&u1.y));
        a0 += n0 * p0.x + n1 * q0.x;
        a1 += n0 * p0.y + n1 * q0.y;
        a2 += n0 * p1.x + n1 * q1.x;
        a3 += n0 * p1.y + n1 * q1.y;
    }
    if (j < e) {
        int   s0 = g_adj_src[j];
        float n0 = g_adj_norm[j];
        uint2 u0 = *(const uint2*)(XH + (size_t)s0 * 128 + lane * 4);
        float2 p0 = __half22float2(*reinterpret_cast<__half2*>(&u0.x));
        float2 p1 = __half22float2(*reinterpret_cast<__half2*>(&u0.y));
        a0 += n0 * p0.x; a1 += n0 * p0.y;
        a2 += n0 * p1.x; a3 += n0 * p1.y;
    }

    float4 bb = ((const float4*)bias)[lane];
    float r[4] = {a0 + bb.x, a1 + bb.y, a2 + bb.z, a3 + bb.w};

    if (ACT == 0) {
        #pragma unroll
        for (int k = 0; k < 4; k++) r[k] = (r[k] > 0.f) ? r[k] : expm1f(r[k]);
    } else if (ACT == 1) {
        #pragma unroll
        for (int k = 0; k < 4; k++)
            r[k] = 0.5f * r[k] * (1.0f + erff(r[k] * 0.70710678118654752f));
    } else {
        float a = *prelu;
        #pragma unroll
        for (int k = 0; k < 4; k++) r[k] = (r[k] >= 0.f) ? r[k] : a * r[k];
    }

    if (WMODE == 0) {
        union { __nv_bfloat16 b[4]; ushort4 u; } H, L;
        #pragma unroll
        for (int k = 0; k < 4; k++) {
            H.b[k] = __float2bfloat16(r[k]);
            L.b[k] = __float2bfloat16(r[k] - __bfloat162float(H.b[k]));
        }
        size_t off = (size_t)node * 128 + lane * 4;
        *(ushort4*)(&g_aHi[off]) = H.u;
        *(ushort4*)(&g_aLo[off]) = L.u;
    } else {
        ((float4*)OUTparam)[(size_t)node * 32 + lane] = make_float4(r[0], r[1], r[2], r[3]);
    }
}

// ---------------- launch ----------------
extern "C" void kernel_launch(void* const* d_in, const int* in_sizes, int n_in,
                              void* d_out, int out_size) {
    const float* x  = (const float*)d_in[0];
    const int*   ei = (const int*)d_in[1];
    const float* w  = (const float*)d_in[2];
    const float* W1 = (const float*)d_in[3];
    const float* b1 = (const float*)d_in[4];
    const float* W2 = (const float*)d_in[5];
    const float* b2 = (const float*)d_in[6];
    const float* W3 = (const float*)d_in[7];
    const float* b3 = (const float*)d_in[8];
    const float* pr = (const float*)d_in[9];

    int n = in_sizes[0] / DDIM;          // 50000
    int e = in_sizes[2];                 // 600000

    int nb256 = (n + 255) / 256;         // 196
    int eb256 = (e + 255) / 256;
    int numTiles = (n + 127) / 128;      // 391
    int aggGrid  = (n + 7) / 8;
    int splitGrid = (n * 32 + 255) / 256;
    int gemmGrid = numTiles < 148 ? numTiles : 148;

    cudaFuncSetAttribute(k_gemm_mma, cudaFuncAttributeMaxDynamicSharedMemorySize, GSMEM);

    // graph normalization + CSR
    k_node_init<<<nb256, 256>>>(n);
    k_edge_pre<<<eb256, 256>>>(ei, w, e);
    k_scan_local<<<nb256, 256>>>(n);
    k_scan_bsums<<<1, 256>>>(nb256);
    k_scan_add_norm<<<nb256, 256>>>(n);
    k_csr_fill<<<eb256, 256>>>(ei, w, e);

    // input split
    k_split_x<<<splitGrid, 256>>>(x, n * 32);

    // layer 1: GCN -> ELU
    k_gemm_mma<<<gemmGrid, 256, GSMEM>>>(W1, n, numTiles);
    k_agg<0, 0><<<aggGrid, 256>>>(nullptr, b1, pr, n);
    // layer 2: GCN -> GELU (exact)
    k_gemm_mma<<<gemmGrid, 256, GSMEM>>>(W2, n, numTiles);
    k_agg<1, 0><<<aggGrid, 256>>>(nullptr, b2, pr, n);
    // layer 3: GCN -> PReLU
    k_gemm_mma<<<gemmGrid, 256, GSMEM>>>(W3, n, numTiles);
    k_agg<2, 1><<<aggGrid, 256>>>((float*)d_out, b3, pr, n);
}